// round 2
// baseline (speedup 1.0000x reference)
#include <cuda_runtime.h>
#include <cstdint>

#define LATENT 128
#define DQ 32            // KQ_DIM
#define BATCH 8
#define NN 16384
#define KK 16
#define ROWS (BATCH * NN)            // 131072
#define BNK  (BATCH * NN * KK)       // 2097152

// scratch: projected keys/queries, fp32, [ROWS][32]
__device__ __align__(128) float g_ks[ROWS * DQ];
__device__ __align__(128) float g_qs[ROWS * DQ];
__device__ int g_idx_is64;

typedef unsigned long long u64;

__device__ __forceinline__ u64 pack2(float lo, float hi) {
    u64 r;
    asm("mov.b64 %0, {%1, %2};" : "=l"(r)
        : "r"(__float_as_uint(lo)), "r"(__float_as_uint(hi)));
    return r;
}
__device__ __forceinline__ void unpack2(u64 v, float& lo, float& hi) {
    unsigned a, b;
    asm("mov.b64 {%0, %1}, %2;" : "=r"(a), "=r"(b) : "l"(v));
    lo = __uint_as_float(a);
    hi = __uint_as_float(b);
}
__device__ __forceinline__ u64 fma2(u64 a, u64 b, u64 c) {
    u64 d;
    asm("fma.rn.f32x2 %0, %1, %2, %3;" : "=l"(d) : "l"(a), "l"(b), "l"(c));
    return d;
}

// ---------------------------------------------------------------------------
// dtype detect: int64 indices with values in [0,16384) have every odd 32-bit
// word == 0. 256 consecutive zero odd-words is impossible for real int32
// index data. One warp, first 512 int32 words (2 KB, in-bounds either way).
// ---------------------------------------------------------------------------
__global__ void detect_idx_kernel(const int* __restrict__ idx32)
{
    int lane = threadIdx.x;            // 32 threads
    int all_hi_zero = 1;
    for (int i = lane; i < 256; i += 32)
        if (idx32[2 * i + 1] != 0) all_hi_zero = 0;
    all_hi_zero = __all_sync(0xffffffffu, all_hi_zero);
    if (lane == 0) g_idx_is64 = all_hi_zero;
}

// ---------------------------------------------------------------------------
// Phase 1: proj[row][d] = features[row] . W[d] + bias[d], 64 combined outputs
// (d<32 -> ks, d>=32 -> qs). One row/thread; weights staged in shared
// transposed+pair-packed: each latent l gives 16 broadcast LDS.128 feeding
// 32 packed fma.rn.f32x2.
// ---------------------------------------------------------------------------
__global__ void __launch_bounds__(256)
proj_kernel(const float* __restrict__ features,
            const float* __restrict__ ks_w, const float* __restrict__ ks_b,
            const float* __restrict__ qs_w, const float* __restrict__ qs_b)
{
    // ws[l*64 + d]: weight for latent l, combined output d
    __shared__ __align__(16) float ws[LATENT * 64];

    for (int i = threadIdx.x; i < LATENT * DQ; i += 256) {
        int d = i / LATENT;       // output dim
        int l = i % LATENT;       // latent dim (W is row-major [32,128])
        ws[l * 64 + d]      = ks_w[i];
        ws[l * 64 + 32 + d] = qs_w[i];
    }
    __syncthreads();

    int row = blockIdx.x * 256 + threadIdx.x;   // grid sized exactly to ROWS

    // acc[i] holds combined outputs (2i, 2i+1) as packed f32x2
    u64 acc[32];
#pragma unroll
    for (int j = 0; j < 16; j++) acc[j]      = pack2(ks_b[2 * j], ks_b[2 * j + 1]);
#pragma unroll
    for (int j = 0; j < 16; j++) acc[16 + j] = pack2(qs_b[2 * j], qs_b[2 * j + 1]);

    const float4* fv = reinterpret_cast<const float4*>(features + (size_t)row * LATENT);

#pragma unroll 2
    for (int lc = 0; lc < LATENT / 4; lc++) {
        float4 f4 = fv[lc];
        float fvals[4] = {f4.x, f4.y, f4.z, f4.w};
#pragma unroll
        for (int i = 0; i < 4; i++) {
            u64 ff = pack2(fvals[i], fvals[i]);
            const ulonglong2* wrow =
                reinterpret_cast<const ulonglong2*>(ws + (lc * 4 + i) * 64);
#pragma unroll
            for (int j = 0; j < 16; j++) {
                ulonglong2 w2 = wrow[j];       // broadcast LDS.128
                acc[2 * j]     = fma2(ff, w2.x, acc[2 * j]);
                acc[2 * j + 1] = fma2(ff, w2.y, acc[2 * j + 1]);
            }
        }
    }

    float4* kout = reinterpret_cast<float4*>(g_ks + (size_t)row * DQ);
    float4* qout = reinterpret_cast<float4*>(g_qs + (size_t)row * DQ);
#pragma unroll
    for (int j = 0; j < 8; j++) {
        float4 v;
        unpack2(acc[2 * j],     v.x, v.y);
        unpack2(acc[2 * j + 1], v.z, v.w);
        kout[j] = v;
    }
#pragma unroll
    for (int j = 0; j < 8; j++) {
        float4 v;
        unpack2(acc[16 + 2 * j],     v.x, v.y);
        unpack2(acc[16 + 2 * j + 1], v.z, v.w);
        qout[j] = v;
    }
}

// ---------------------------------------------------------------------------
// Phase 2: out[b,n,k] = (g_ks[b, x_idx] . g_qs[b, y_idx]) * 32^-0.5
// One thread per logit; index loads coalesced; gathers are 128B rows that
// hit L2 (per-batch tables are 2MB each).
// ---------------------------------------------------------------------------
__global__ void __launch_bounds__(256)
affinity_kernel(const void* __restrict__ indices_raw, float* __restrict__ out)
{
    int tid = blockIdx.x * 256 + threadIdx.x;   // grid sized exactly to BNK

    int b = tid >> 18;                          // N*K = 2^18
    long long x, y;
    if (g_idx_is64) {
        const long long* idx = (const long long*)indices_raw;
        x = idx[(size_t)BNK + tid];             // channel 1
        y = idx[(size_t)2 * BNK + tid];         // channel 2
    } else {
        const int* idx = (const int*)indices_raw;
        x = idx[(size_t)BNK + tid];
        y = idx[(size_t)2 * BNK + tid];
    }

    size_t xrow = (((size_t)b << 14) + (size_t)x) * DQ;
    size_t yrow = (((size_t)b << 14) + (size_t)y) * DQ;

    const float4* xa = reinterpret_cast<const float4*>(g_ks + xrow);
    const float4* ya = reinterpret_cast<const float4*>(g_qs + yrow);

    float s = 0.0f;
#pragma unroll
    for (int j = 0; j < 8; j++) {
        float4 a = xa[j];
        float4 c = ya[j];
        s += a.x * c.x + a.y * c.y + a.z * c.z + a.w * c.w;
    }

    out[tid] = s * 0.17677669529663687f;        // 32^-0.5
}

extern "C" void kernel_launch(void* const* d_in, const int* in_sizes, int n_in,
                              void* d_out, int out_size)
{
    const float* features = (const float*)d_in[0];
    const float* ks_w     = (const float*)d_in[1];
    const float* ks_b     = (const float*)d_in[2];
    const float* qs_w     = (const float*)d_in[3];
    const float* qs_b     = (const float*)d_in[4];
    const void*  indices  = d_in[5];
    float*       out      = (float*)d_out;

    detect_idx_kernel<<<1, 32>>>((const int*)indices);
    proj_kernel<<<ROWS / 256, 256>>>(features, ks_w, ks_b, qs_w, qs_b);
    affinity_kernel<<<BNK / 256, 256>>>(indices, out);
}

// round 3
// speedup vs baseline: 1.1186x; 1.1186x over previous
#include <cuda_runtime.h>
#include <cstdint>

#define LATENT 128
#define DQ 32            // KQ_DIM
#define BATCH 8
#define NN 16384
#define KK 16
#define ROWS (BATCH * NN)            // 131072
#define BNK  (BATCH * NN * KK)       // 2097152

// scratch: projected keys/queries, fp32, [ROWS][32] (128B rows, 128B aligned)
__device__ __align__(128) float g_ks[ROWS * DQ];
__device__ __align__(128) float g_qs[ROWS * DQ];
__device__ int g_idx_is64;

typedef unsigned long long u64;

__device__ __forceinline__ u64 pack2(float lo, float hi) {
    u64 r;
    asm("mov.b64 %0, {%1, %2};" : "=l"(r)
        : "r"(__float_as_uint(lo)), "r"(__float_as_uint(hi)));
    return r;
}
__device__ __forceinline__ void unpack2(u64 v, float& lo, float& hi) {
    unsigned a, b;
    asm("mov.b64 {%0, %1}, %2;" : "=r"(a), "=r"(b) : "l"(v));
    lo = __uint_as_float(a);
    hi = __uint_as_float(b);
}
__device__ __forceinline__ u64 fma2(u64 a, u64 b, u64 c) {
    u64 d;
    asm("fma.rn.f32x2 %0, %1, %2, %3;" : "=l"(d) : "l"(a), "l"(b), "l"(c));
    return d;
}

// ---------------------------------------------------------------------------
// Phase 1: proj[row][d] = features[row] . W[d] + bias[d], 64 combined outputs
// (d<32 -> ks, d>=32 -> qs). One row/thread; weights staged in shared
// transposed+pair-packed: each latent l gives 16 broadcast LDS.128 feeding
// 32 packed fma.rn.f32x2. Block 0 / warp 0 also does the index-dtype detect
// (odd 32-bit words of small nonneg int64 are all zero; impossible for 256
// consecutive genuine int32 indices).
// ---------------------------------------------------------------------------
__global__ void __launch_bounds__(256)
proj_kernel(const float* __restrict__ features,
            const float* __restrict__ ks_w, const float* __restrict__ ks_b,
            const float* __restrict__ qs_w, const float* __restrict__ qs_b,
            const int*   __restrict__ idx32)
{
    if (blockIdx.x == 0 && threadIdx.x < 32) {
        int lane = threadIdx.x;
        int all_hi_zero = 1;
        for (int i = lane; i < 256; i += 32)
            if (idx32[2 * i + 1] != 0) all_hi_zero = 0;
        all_hi_zero = __all_sync(0xffffffffu, all_hi_zero);
        if (lane == 0) g_idx_is64 = all_hi_zero;
    }

    // ws[l*64 + d]: weight for latent l, combined output d
    __shared__ __align__(16) float ws[LATENT * 64];

    for (int i = threadIdx.x; i < LATENT * DQ; i += 256) {
        int d = i / LATENT;       // output dim
        int l = i % LATENT;       // latent dim (W is row-major [32,128])
        ws[l * 64 + d]      = ks_w[i];
        ws[l * 64 + 32 + d] = qs_w[i];
    }
    __syncthreads();

    int row = blockIdx.x * 256 + threadIdx.x;   // grid sized exactly to ROWS

    // acc[i] holds combined outputs (2i, 2i+1) as packed f32x2
    u64 acc[32];
#pragma unroll
    for (int j = 0; j < 16; j++) acc[j]      = pack2(ks_b[2 * j], ks_b[2 * j + 1]);
#pragma unroll
    for (int j = 0; j < 16; j++) acc[16 + j] = pack2(qs_b[2 * j], qs_b[2 * j + 1]);

    const float4* fv = reinterpret_cast<const float4*>(features + (size_t)row * LATENT);

#pragma unroll 2
    for (int lc = 0; lc < LATENT / 4; lc++) {
        float4 f4 = fv[lc];
        float fvals[4] = {f4.x, f4.y, f4.z, f4.w};
#pragma unroll
        for (int i = 0; i < 4; i++) {
            u64 ff = pack2(fvals[i], fvals[i]);
            const ulonglong2* wrow =
                reinterpret_cast<const ulonglong2*>(ws + (lc * 4 + i) * 64);
#pragma unroll
            for (int j = 0; j < 16; j++) {
                ulonglong2 w2 = wrow[j];       // broadcast LDS.128
                acc[2 * j]     = fma2(ff, w2.x, acc[2 * j]);
                acc[2 * j + 1] = fma2(ff, w2.y, acc[2 * j + 1]);
            }
        }
    }

    float4* kout = reinterpret_cast<float4*>(g_ks + (size_t)row * DQ);
    float4* qout = reinterpret_cast<float4*>(g_qs + (size_t)row * DQ);
#pragma unroll
    for (int j = 0; j < 8; j++) {
        float4 v;
        unpack2(acc[2 * j],     v.x, v.y);
        unpack2(acc[2 * j + 1], v.z, v.w);
        kout[j] = v;
    }
#pragma unroll
    for (int j = 0; j < 8; j++) {
        float4 v;
        unpack2(acc[16 + 2 * j],     v.x, v.y);
        unpack2(acc[16 + 2 * j + 1], v.z, v.w);
        qout[j] = v;
    }
}

// ---------------------------------------------------------------------------
// Phase 2: out[b,n,k] = (g_ks[b, x_idx] . g_qs[b, y_idx]) * 32^-0.5
// Cooperative gather: 8 lanes per logit, each lane loads one float4 of the
// 128B row -> each warp-level LDG.128 touches only 4 distinct lines
// (4 wavefronts instead of 32). 3x shfl_xor reduces the dot within the group.
// ---------------------------------------------------------------------------
__global__ void __launch_bounds__(256)
affinity_kernel(const void* __restrict__ indices_raw, float* __restrict__ out)
{
    int t   = blockIdx.x * 256 + threadIdx.x;   // 8 threads per logit
    int lid = t >> 3;                           // logit id, < BNK
    int sub = t & 7;

    int b = lid >> 18;                          // N*K = 2^18
    long long x, y;
    if (g_idx_is64) {
        const long long* idx = (const long long*)indices_raw;
        x = idx[(size_t)BNK + lid];             // channel 1
        y = idx[(size_t)2 * BNK + lid];         // channel 2
    } else {
        const int* idx = (const int*)indices_raw;
        x = idx[(size_t)BNK + lid];
        y = idx[(size_t)2 * BNK + lid];
    }

    size_t xrow = (((size_t)b << 14) + (size_t)x) << 5;   // *DQ
    size_t yrow = (((size_t)b << 14) + (size_t)y) << 5;

    float4 a = reinterpret_cast<const float4*>(g_ks + xrow)[sub];
    float4 c = reinterpret_cast<const float4*>(g_qs + yrow)[sub];

    float s = a.x * c.x + a.y * c.y + a.z * c.z + a.w * c.w;
    s += __shfl_xor_sync(0xffffffffu, s, 4);
    s += __shfl_xor_sync(0xffffffffu, s, 2);
    s += __shfl_xor_sync(0xffffffffu, s, 1);

    if (sub == 0) out[lid] = s * 0.17677669529663687f;    // 32^-0.5
}

extern "C" void kernel_launch(void* const* d_in, const int* in_sizes, int n_in,
                              void* d_out, int out_size)
{
    const float* features = (const float*)d_in[0];
    const float* ks_w     = (const float*)d_in[1];
    const float* ks_b     = (const float*)d_in[2];
    const float* qs_w     = (const float*)d_in[3];
    const float* qs_b     = (const float*)d_in[4];
    const void*  indices  = d_in[5];
    float*       out      = (float*)d_out;

    proj_kernel<<<ROWS / 256, 256>>>(features, ks_w, ks_b, qs_w, qs_b,
                                     (const int*)indices);
    affinity_kernel<<<(size_t)BNK * 8 / 256, 256>>>(indices, out);
}

// round 5
// speedup vs baseline: 1.1274x; 1.0079x over previous
#include <cuda_runtime.h>
#include <cstdint>

#define LATENT 128
#define DQ 32            // KQ_DIM
#define BATCH 8
#define NN 16384
#define KK 16
#define ROWS (BATCH * NN)            // 131072
#define BNK  (BATCH * NN * KK)       // 2097152

// scratch: projected keys/queries, fp32, [ROWS][32] (128B rows, 128B aligned)
__device__ __align__(128) float g_ks[ROWS * DQ];
__device__ __align__(128) float g_qs[ROWS * DQ];
__device__ int g_idx_is64;

typedef unsigned long long u64;

__device__ __forceinline__ u64 pack2(float lo, float hi) {
    u64 r;
    asm("mov.b64 %0, {%1, %2};" : "=l"(r)
        : "r"(__float_as_uint(lo)), "r"(__float_as_uint(hi)));
    return r;
}
__device__ __forceinline__ void unpack2(u64 v, float& lo, float& hi) {
    unsigned a, b;
    asm("mov.b64 {%0, %1}, %2;" : "=r"(a), "=r"(b) : "l"(v));
    lo = __uint_as_float(a);
    hi = __uint_as_float(b);
}
__device__ __forceinline__ u64 fma2(u64 a, u64 b, u64 c) {
    u64 d;
    asm("fma.rn.f32x2 %0, %1, %2, %3;" : "=l"(d) : "l"(a), "l"(b), "l"(c));
    return d;
}

// ---------------------------------------------------------------------------
// Phase 1 (one matrix per kernel, low register pressure):
//   table[row][d] = features[row] . W[d] + b[d], d in [0,32)
// TO_KS selects g_ks vs g_qs INSIDE device code (never pass __device__
// globals as host-side kernel args!). One row per thread; weights staged in
// shared transposed+pair-packed: per latent l, 8 broadcast LDS.128 feed 16
// packed fma.rn.f32x2.
// DO_DETECT: block 0 / warp 0 detects index dtype (odd 32-bit words of small
// nonneg int64 are all zero; impossible for 256 genuine int32 indices).
// ---------------------------------------------------------------------------
template <bool DO_DETECT, bool TO_KS>
__global__ void __launch_bounds__(256)
proj_half_kernel(const float* __restrict__ features,
                 const float* __restrict__ W,   // [32][128] row-major
                 const float* __restrict__ bias,
                 const int*   __restrict__ idx32)
{
    if (DO_DETECT && blockIdx.x == 0 && threadIdx.x < 32) {
        int lane = threadIdx.x;
        int all_hi_zero = 1;
        for (int i = lane; i < 256; i += 32)
            if (idx32[2 * i + 1] != 0) all_hi_zero = 0;
        all_hi_zero = __all_sync(0xffffffffu, all_hi_zero);
        if (lane == 0) g_idx_is64 = all_hi_zero;
    }

    float* __restrict__ outp = TO_KS ? g_ks : g_qs;

    // ws[l*32 + d]: weight for latent l, output d
    __shared__ __align__(16) float ws[LATENT * DQ];

    for (int i = threadIdx.x; i < LATENT * DQ; i += 256) {
        int d = i >> 7;          // W row-major [32][128]
        int l = i & 127;
        ws[l * DQ + d] = W[i];
    }
    __syncthreads();

    int row = blockIdx.x * 256 + threadIdx.x;   // grid sized exactly to ROWS

    // acc[j] holds outputs (2j, 2j+1) as packed f32x2
    u64 acc[16];
#pragma unroll
    for (int j = 0; j < 16; j++) acc[j] = pack2(bias[2 * j], bias[2 * j + 1]);

    const float4* fv = reinterpret_cast<const float4*>(features + (size_t)row * LATENT);

    for (int lc = 0; lc < LATENT / 4; lc++) {
        float4 f4 = fv[lc];
        float fvals[4] = {f4.x, f4.y, f4.z, f4.w};
#pragma unroll
        for (int i = 0; i < 4; i++) {
            u64 ff = pack2(fvals[i], fvals[i]);
            const ulonglong2* wrow =
                reinterpret_cast<const ulonglong2*>(ws + (lc * 4 + i) * DQ);
#pragma unroll
            for (int j = 0; j < 8; j++) {
                ulonglong2 w2 = wrow[j];        // broadcast LDS.128
                acc[2 * j]     = fma2(ff, w2.x, acc[2 * j]);
                acc[2 * j + 1] = fma2(ff, w2.y, acc[2 * j + 1]);
            }
        }
    }

    float4* po = reinterpret_cast<float4*>(outp + (size_t)row * DQ);
#pragma unroll
    for (int j = 0; j < 8; j++) {
        float4 v;
        unpack2(acc[2 * j],     v.x, v.y);
        unpack2(acc[2 * j + 1], v.z, v.w);
        po[j] = v;
    }
}

// ---------------------------------------------------------------------------
// Phase 2: out[b,n,k] = (g_ks[b, x_idx] . g_qs[b, y_idx]) * 32^-0.5
// 8 lanes per logit; each group handles TWO adjacent logits so every thread
// has 4 independent float4 gathers in flight (MLP=4). Each warp-level
// LDG.128 touches 4 distinct 128B rows = 4 wavefronts. 3x shfl_xor per logit
// reduces the dot across the 8-lane group; lane 0 stores a float2.
// ---------------------------------------------------------------------------
__global__ void __launch_bounds__(256)
affinity_kernel(const void* __restrict__ indices_raw, float* __restrict__ out)
{
    int t   = blockIdx.x * 256 + threadIdx.x;
    int g   = t >> 3;                 // logit-pair id, < BNK/2
    int sub = t & 7;

    int lid0 = g << 1;
    int lid1 = lid0 | 1;
    int b    = lid0 >> 18;            // N*K = 2^18 (lid0,lid1 share batch)

    long long x0, y0, x1, y1;
    if (g_idx_is64) {
        const long long* idx = (const long long*)indices_raw;
        x0 = idx[(size_t)BNK + lid0];
        x1 = idx[(size_t)BNK + lid1];
        y0 = idx[(size_t)2 * BNK + lid0];
        y1 = idx[(size_t)2 * BNK + lid1];
    } else {
        const int* idx = (const int*)indices_raw;
        x0 = idx[(size_t)BNK + lid0];
        x1 = idx[(size_t)BNK + lid1];
        y0 = idx[(size_t)2 * BNK + lid0];
        y1 = idx[(size_t)2 * BNK + lid1];
    }

    size_t base = (size_t)b << 14;
    const float4* xa0 = reinterpret_cast<const float4*>(g_ks + ((base + (size_t)x0) << 5));
    const float4* ya0 = reinterpret_cast<const float4*>(g_qs + ((base + (size_t)y0) << 5));
    const float4* xa1 = reinterpret_cast<const float4*>(g_ks + ((base + (size_t)x1) << 5));
    const float4* ya1 = reinterpret_cast<const float4*>(g_qs + ((base + (size_t)y1) << 5));

    float4 a0 = xa0[sub];
    float4 c0 = ya0[sub];
    float4 a1 = xa1[sub];
    float4 c1 = ya1[sub];

    float s0 = a0.x * c0.x + a0.y * c0.y + a0.z * c0.z + a0.w * c0.w;
    float s1 = a1.x * c1.x + a1.y * c1.y + a1.z * c1.z + a1.w * c1.w;

#pragma unroll
    for (int m = 4; m >= 1; m >>= 1) {
        s0 += __shfl_xor_sync(0xffffffffu, s0, m);
        s1 += __shfl_xor_sync(0xffffffffu, s1, m);
    }

    if (sub == 0) {
        float2 o = make_float2(s0 * 0.17677669529663687f,
                               s1 * 0.17677669529663687f);  // 32^-0.5
        *reinterpret_cast<float2*>(out + lid0) = o;
    }
}

extern "C" void kernel_launch(void* const* d_in, const int* in_sizes, int n_in,
                              void* d_out, int out_size)
{
    const float* features = (const float*)d_in[0];
    const float* ks_w     = (const float*)d_in[1];
    const float* ks_b     = (const float*)d_in[2];
    const float* qs_w     = (const float*)d_in[3];
    const float* qs_b     = (const float*)d_in[4];
    const void*  indices  = d_in[5];
    float*       out      = (float*)d_out;

    proj_half_kernel<true,  true ><<<ROWS / 256, 256>>>(features, ks_w, ks_b,
                                                        (const int*)indices);
    proj_half_kernel<false, false><<<ROWS / 256, 256>>>(features, qs_w, qs_b,
                                                        (const int*)indices);
    // 8 lanes x (BNK/2) logit-pairs
    affinity_kernel<<<(BNK / 2) * 8 / 256, 256>>>(indices, out);
}

// round 6
// speedup vs baseline: 1.3149x; 1.1663x over previous
#include <cuda_runtime.h>
#include <cstdint>

#define LATENT 128
#define DQ 32            // KQ_DIM
#define BATCH 8
#define NN 16384
#define KK 16
#define ROWS (BATCH * NN)            // 131072
#define BNK  (BATCH * NN * KK)       // 2097152

// scratch: projected keys/queries, fp32, [ROWS][32] (128B rows, 128B aligned)
__device__ __align__(128) float g_ks[ROWS * DQ];
__device__ __align__(128) float g_qs[ROWS * DQ];
__device__ int g_idx_is64;

typedef unsigned long long u64;

__device__ __forceinline__ u64 pack2(float lo, float hi) {
    u64 r;
    asm("mov.b64 %0, {%1, %2};" : "=l"(r)
        : "r"(__float_as_uint(lo)), "r"(__float_as_uint(hi)));
    return r;
}
__device__ __forceinline__ void unpack2(u64 v, float& lo, float& hi) {
    unsigned a, b;
    asm("mov.b64 {%0, %1}, %2;" : "=r"(a), "=r"(b) : "l"(v));
    lo = __uint_as_float(a);
    hi = __uint_as_float(b);
}
__device__ __forceinline__ u64 fma2(u64 a, u64 b, u64 c) {
    u64 d;
    asm("fma.rn.f32x2 %0, %1, %2, %3;" : "=l"(d) : "l"(a), "l"(b), "l"(c));
    return d;
}

// ---------------------------------------------------------------------------
// Phase 1 (fused, single features pass): for each row,
//   g_ks[row][d] = features[row] . ks_w[d] + ks_b[d]
//   g_qs[row][d] = features[row] . qs_w[d] + qs_b[d]
// One row per thread. 64 combined outputs as 32 packed-f32x2 accumulators.
// Weights staged in shared transposed+pair-packed: per latent l, 16 broadcast
// LDS.128 feed 32 fma.rn.f32x2 (lanes = different rows, same latent => N=1).
// Feature stream is software-pipelined: 8-latent chunks, next chunk's two
// LDG.128 issued before processing the current chunk (hides L2/DRAM latency
// that made round-5's MLP=1 loop stall at issue=24%).
// Block 0 / warp 0 also detects index dtype (odd 32-bit words of small nonneg
// int64 are all zero; impossible for 256 genuine int32 indices).
// ---------------------------------------------------------------------------
template <bool DO_DETECT>
__global__ void __launch_bounds__(256, 2)
proj_fused_kernel(const float* __restrict__ features,
                  const float* __restrict__ ks_w, const float* __restrict__ ks_b,
                  const float* __restrict__ qs_w, const float* __restrict__ qs_b,
                  const int*   __restrict__ idx32)
{
    if (DO_DETECT && blockIdx.x == 0 && threadIdx.x < 32) {
        int lane = threadIdx.x;
        int all_hi_zero = 1;
        for (int i = lane; i < 256; i += 32)
            if (idx32[2 * i + 1] != 0) all_hi_zero = 0;
        all_hi_zero = __all_sync(0xffffffffu, all_hi_zero);
        if (lane == 0) g_idx_is64 = all_hi_zero;
    }

    // ws[l*64 + d]: weight for latent l, combined output d (d<32: ks, else qs)
    __shared__ __align__(16) float ws[LATENT * 64];

    for (int i = threadIdx.x; i < LATENT * DQ; i += 256) {
        int d = i >> 7;          // W row-major [32][128]
        int l = i & 127;
        ws[l * 64 + d]      = ks_w[i];
        ws[l * 64 + 32 + d] = qs_w[i];
    }
    __syncthreads();

    int row = blockIdx.x * 256 + threadIdx.x;   // grid sized exactly to ROWS

    // acc[j] holds combined outputs (2j, 2j+1) as packed f32x2
    u64 acc[32];
#pragma unroll
    for (int j = 0; j < 16; j++) acc[j]      = pack2(ks_b[2 * j], ks_b[2 * j + 1]);
#pragma unroll
    for (int j = 0; j < 16; j++) acc[16 + j] = pack2(qs_b[2 * j], qs_b[2 * j + 1]);

    const float4* fv = reinterpret_cast<const float4*>(features + (size_t)row * LATENT);

    // software pipeline: 16 chunks of 8 latents (2 float4 each)
    float4 buf0 = fv[0];
    float4 buf1 = fv[1];

#pragma unroll
    for (int chunk = 0; chunk < 16; chunk++) {
        float4 cur0 = buf0;
        float4 cur1 = buf1;
        if (chunk < 15) {                 // prefetch next chunk early
            buf0 = fv[2 * chunk + 2];
            buf1 = fv[2 * chunk + 3];
        }
        float fvals[8] = {cur0.x, cur0.y, cur0.z, cur0.w,
                          cur1.x, cur1.y, cur1.z, cur1.w};
#pragma unroll
        for (int i = 0; i < 8; i++) {
            u64 ff = pack2(fvals[i], fvals[i]);
            const ulonglong2* wrow =
                reinterpret_cast<const ulonglong2*>(ws + (chunk * 8 + i) * 64);
#pragma unroll
            for (int j = 0; j < 16; j++) {
                ulonglong2 w2 = wrow[j];       // broadcast LDS.128
                acc[2 * j]     = fma2(ff, w2.x, acc[2 * j]);
                acc[2 * j + 1] = fma2(ff, w2.y, acc[2 * j + 1]);
            }
        }
    }

    float4* kout = reinterpret_cast<float4*>(g_ks + (size_t)row * DQ);
    float4* qout = reinterpret_cast<float4*>(g_qs + (size_t)row * DQ);
#pragma unroll
    for (int j = 0; j < 8; j++) {
        float4 v;
        unpack2(acc[2 * j],     v.x, v.y);
        unpack2(acc[2 * j + 1], v.z, v.w);
        kout[j] = v;
    }
#pragma unroll
    for (int j = 0; j < 8; j++) {
        float4 v;
        unpack2(acc[16 + 2 * j],     v.x, v.y);
        unpack2(acc[16 + 2 * j + 1], v.z, v.w);
        qout[j] = v;
    }
}

// ---------------------------------------------------------------------------
// Phase 2: out[b,n,k] = (g_ks[b, x_idx] . g_qs[b, y_idx]) * 32^-0.5
// 8 lanes per logit; each group handles TWO adjacent logits so every thread
// has 4 independent float4 gathers in flight (MLP=4). Each warp-level
// LDG.128 touches 4 distinct 128B rows = 4 wavefronts. 3x shfl_xor per logit
// reduces the dot across the 8-lane group; lane 0 stores a float2.
// ---------------------------------------------------------------------------
__global__ void __launch_bounds__(256)
affinity_kernel(const void* __restrict__ indices_raw, float* __restrict__ out)
{
    int t   = blockIdx.x * 256 + threadIdx.x;
    int g   = t >> 3;                 // logit-pair id, < BNK/2
    int sub = t & 7;

    int lid0 = g << 1;
    int lid1 = lid0 | 1;
    int b    = lid0 >> 18;            // N*K = 2^18 (lid0,lid1 share batch)

    long long x0, y0, x1, y1;
    if (g_idx_is64) {
        const long long* idx = (const long long*)indices_raw;
        x0 = idx[(size_t)BNK + lid0];
        x1 = idx[(size_t)BNK + lid1];
        y0 = idx[(size_t)2 * BNK + lid0];
        y1 = idx[(size_t)2 * BNK + lid1];
    } else {
        const int* idx = (const int*)indices_raw;
        x0 = idx[(size_t)BNK + lid0];
        x1 = idx[(size_t)BNK + lid1];
        y0 = idx[(size_t)2 * BNK + lid0];
        y1 = idx[(size_t)2 * BNK + lid1];
    }

    size_t base = (size_t)b << 14;
    const float4* xa0 = reinterpret_cast<const float4*>(g_ks + ((base + (size_t)x0) << 5));
    const float4* ya0 = reinterpret_cast<const float4*>(g_qs + ((base + (size_t)y0) << 5));
    const float4* xa1 = reinterpret_cast<const float4*>(g_ks + ((base + (size_t)x1) << 5));
    const float4* ya1 = reinterpret_cast<const float4*>(g_qs + ((base + (size_t)y1) << 5));

    float4 a0 = xa0[sub];
    float4 c0 = ya0[sub];
    float4 a1 = xa1[sub];
    float4 c1 = ya1[sub];

    float s0 = a0.x * c0.x + a0.y * c0.y + a0.z * c0.z + a0.w * c0.w;
    float s1 = a1.x * c1.x + a1.y * c1.y + a1.z * c1.z + a1.w * c1.w;

#pragma unroll
    for (int m = 4; m >= 1; m >>= 1) {
        s0 += __shfl_xor_sync(0xffffffffu, s0, m);
        s1 += __shfl_xor_sync(0xffffffffu, s1, m);
    }

    if (sub == 0) {
        float2 o = make_float2(s0 * 0.17677669529663687f,
                               s1 * 0.17677669529663687f);  // 32^-0.5
        *reinterpret_cast<float2*>(out + lid0) = o;
    }
}

extern "C" void kernel_launch(void* const* d_in, const int* in_sizes, int n_in,
                              void* d_out, int out_size)
{
    const float* features = (const float*)d_in[0];
    const float* ks_w     = (const float*)d_in[1];
    const float* ks_b     = (const float*)d_in[2];
    const float* qs_w     = (const float*)d_in[3];
    const float* qs_b     = (const float*)d_in[4];
    const void*  indices  = d_in[5];
    float*       out      = (float*)d_out;

    proj_fused_kernel<true><<<ROWS / 256, 256>>>(features, ks_w, ks_b,
                                                 qs_w, qs_b,
                                                 (const int*)indices);
    // 8 lanes x (BNK/2) logit-pairs
    affinity_kernel<<<(BNK / 2) * 8 / 256, 256>>>(indices, out);
}

// round 7
// speedup vs baseline: 1.3569x; 1.0319x over previous
#include <cuda_runtime.h>
#include <cuda_fp16.h>
#include <cstdint>

#define LATENT 128
#define DQ 32            // KQ_DIM
#define BATCH 8
#define NN 16384
#define KK 16
#define ROWS (BATCH * NN)            // 131072
#define BNK  (BATCH * NN * KK)       // 2097152

// combined projection table, fp16: row r has 64 halves = ks[0:32) | qs[32:64)
// row stride 128 bytes, 128B aligned.
__device__ __align__(128) __half g_kq[ROWS * 64];
__device__ int g_idx_is64;

typedef unsigned long long u64;

__device__ __forceinline__ u64 pack2(float lo, float hi) {
    u64 r;
    asm("mov.b64 %0, {%1, %2};" : "=l"(r)
        : "r"(__float_as_uint(lo)), "r"(__float_as_uint(hi)));
    return r;
}
__device__ __forceinline__ void unpack2(u64 v, float& lo, float& hi) {
    unsigned a, b;
    asm("mov.b64 {%0, %1}, %2;" : "=r"(a), "=r"(b) : "l"(v));
    lo = __uint_as_float(a);
    hi = __uint_as_float(b);
}
__device__ __forceinline__ u64 fma2(u64 a, u64 b, u64 c) {
    u64 d;
    asm("fma.rn.f32x2 %0, %1, %2, %3;" : "=l"(d) : "l"(a), "l"(b), "l"(c));
    return d;
}

// ---------------------------------------------------------------------------
// Phase 1: g_kq[row][d] = features[row].W[d] + b[d] (d<32: ks, d>=32: qs),
// stored fp16.
// Tiling: each thread owns 4 consecutive rows x 16 combined outputs.
//   lane = q*4 + g   (q = row-quad within warp, g = output group)
//   warp covers 32 rows x 64 outputs.
// Per latent: 4 broadcast LDS.128 (16 weights, 8 f32x2 pairs) feed
// 4 rows x 8 = 32 fma.rn.f32x2  -> LDS:FFMA2 = 1:8 (was 1:2).
// Feature LDGs from the 4 output-groups hit identical addresses (merged by
// the coalescer), so features stream from DRAM once.
// Block 0 / warp 0 detects index dtype (odd 32-bit words of small nonneg
// int64 are all zero; impossible for 256 genuine int32 indices).
// ---------------------------------------------------------------------------
template <bool DO_DETECT>
__global__ void __launch_bounds__(128)
proj_kernel(const float* __restrict__ features,
            const float* __restrict__ ks_w, const float* __restrict__ ks_b,
            const float* __restrict__ qs_w, const float* __restrict__ qs_b,
            const int*   __restrict__ idx32)
{
    if (DO_DETECT && blockIdx.x == 0 && threadIdx.x < 32) {
        int lane = threadIdx.x;
        int all_hi_zero = 1;
        for (int i = lane; i < 256; i += 32)
            if (idx32[2 * i + 1] != 0) all_hi_zero = 0;
        all_hi_zero = __all_sync(0xffffffffu, all_hi_zero);
        if (lane == 0) g_idx_is64 = all_hi_zero;
    }

    // ws[l*64 + d]: weight for latent l, combined output d
    __shared__ __align__(16) float ws[LATENT * 64];

    for (int i = threadIdx.x; i < LATENT * DQ; i += 128) {
        int d = i >> 7;          // W row-major [32][128]
        int l = i & 127;
        ws[l * 64 + d]      = ks_w[i];
        ws[l * 64 + 32 + d] = qs_w[i];
    }
    __syncthreads();

    int warp = threadIdx.x >> 5;
    int lane = threadIdx.x & 31;
    int q    = lane >> 2;            // row quad within warp
    int g    = lane & 3;             // output group (16 combined outputs)

    int rowbase = (blockIdx.x * 4 + warp) * 32 + q * 4;   // rows rowbase..+3

    // bias for this thread's 16 combined outputs [16g, 16g+16)
    const float* bsel = (g < 2) ? (ks_b + 16 * g) : (qs_b + (16 * g - 32));

    // acc[j][p]: row rowbase+j, combined outputs (16g+2p, 16g+2p+1) as f32x2
    u64 acc[4][8];
#pragma unroll
    for (int p = 0; p < 8; p++) {
        u64 binit = pack2(bsel[2 * p], bsel[2 * p + 1]);
#pragma unroll
        for (int j = 0; j < 4; j++) acc[j][p] = binit;
    }

    const float4* fvbase = reinterpret_cast<const float4*>(
        features + (size_t)rowbase * LATENT);   // row j at fvbase + j*32

#pragma unroll 4
    for (int c = 0; c < 32; c++) {              // 4 latents per chunk
        float4 f[4];
#pragma unroll
        for (int j = 0; j < 4; j++) f[j] = fvbase[j * 32 + c];  // MLP=4, merged across g

#pragma unroll
        for (int i = 0; i < 4; i++) {
            int l = c * 4 + i;
            const ulonglong2* wrow =
                reinterpret_cast<const ulonglong2*>(ws + l * 64 + 16 * g);
            ulonglong2 wa = wrow[0];            // broadcast LDS.128 x2
            ulonglong2 wb = wrow[1];
            u64 wp[8];
            {
                ulonglong2 wc = wrow[2];
                ulonglong2 wd = wrow[3];
                wp[0] = wa.x; wp[1] = wa.y; wp[2] = wb.x; wp[3] = wb.y;
                wp[4] = wc.x; wp[5] = wc.y; wp[6] = wd.x; wp[7] = wd.y;
            }
#pragma unroll
            for (int j = 0; j < 4; j++) {
                float fj = (i == 0) ? f[j].x : (i == 1) ? f[j].y
                         : (i == 2) ? f[j].z : f[j].w;
                u64 ff = pack2(fj, fj);
#pragma unroll
                for (int p = 0; p < 8; p++)
                    acc[j][p] = fma2(ff, wp[p], acc[j][p]);
            }
        }
    }

    // store fp16: row rowbase+j, halves [16g, 16g+16) = 32 bytes = 2 uint4
#pragma unroll
    for (int j = 0; j < 4; j++) {
        uint4 v0, v1;
        __half2* h0 = reinterpret_cast<__half2*>(&v0);
        __half2* h1 = reinterpret_cast<__half2*>(&v1);
#pragma unroll
        for (int p = 0; p < 4; p++) {
            float lo, hi;
            unpack2(acc[j][p], lo, hi);
            h0[p] = __floats2half2_rn(lo, hi);
        }
#pragma unroll
        for (int p = 0; p < 4; p++) {
            float lo, hi;
            unpack2(acc[j][4 + p], lo, hi);
            h1[p] = __floats2half2_rn(lo, hi);
        }
        uint4* dst = reinterpret_cast<uint4*>(
            g_kq + (size_t)(rowbase + j) * 64 + 16 * g);
        dst[0] = v0;
        dst[1] = v1;
    }
}

// ---------------------------------------------------------------------------
// Phase 2: out[b,n,k] = (ks[b,x_idx] . qs[b,y_idx]) * 32^-0.5, fp16 tables.
// 4 lanes per logit (rows are 64B now); each 4-lane group handles TWO
// adjacent logits (4 independent 16B gathers in flight per thread). 2x
// shfl_xor reduces within the group; lane 0 stores a float2.
// ---------------------------------------------------------------------------
__global__ void __launch_bounds__(256)
affinity_kernel(const void* __restrict__ indices_raw, float* __restrict__ out)
{
    int t   = blockIdx.x * 256 + threadIdx.x;
    int g   = t >> 2;                 // logit-pair id, < BNK/2
    int sub = t & 3;

    int lid0 = g << 1;
    int lid1 = lid0 | 1;
    int b    = lid0 >> 18;            // N*K = 2^18 (pair shares batch)

    long long x0, y0, x1, y1;
    if (g_idx_is64) {
        const long long* idx = (const long long*)indices_raw;
        x0 = idx[(size_t)BNK + lid0];
        x1 = idx[(size_t)BNK + lid1];
        y0 = idx[(size_t)2 * BNK + lid0];
        y1 = idx[(size_t)2 * BNK + lid1];
    } else {
        const int* idx = (const int*)indices_raw;
        x0 = idx[(size_t)BNK + lid0];
        x1 = idx[(size_t)BNK + lid1];
        y0 = idx[(size_t)2 * BNK + lid0];
        y1 = idx[(size_t)2 * BNK + lid1];
    }

    size_t base = (size_t)b << 14;
    // ks half of row: halves [0,32); qs half: [32,64). Lane sub reads 8 halves.
    const uint4* px0 = reinterpret_cast<const uint4*>(g_kq + ((base + (size_t)x0) << 6)) + sub;
    const uint4* py0 = reinterpret_cast<const uint4*>(g_kq + ((base + (size_t)y0) << 6) + 32) + sub;
    const uint4* px1 = reinterpret_cast<const uint4*>(g_kq + ((base + (size_t)x1) << 6)) + sub;
    const uint4* py1 = reinterpret_cast<const uint4*>(g_kq + ((base + (size_t)y1) << 6) + 32) + sub;

    uint4 ax0 = *px0;
    uint4 ay0 = *py0;
    uint4 ax1 = *px1;
    uint4 ay1 = *py1;

    const __half2* hx0 = reinterpret_cast<const __half2*>(&ax0);
    const __half2* hy0 = reinterpret_cast<const __half2*>(&ay0);
    const __half2* hx1 = reinterpret_cast<const __half2*>(&ax1);
    const __half2* hy1 = reinterpret_cast<const __half2*>(&ay1);

    float s0 = 0.0f, s1 = 0.0f;
#pragma unroll
    for (int i = 0; i < 4; i++) {
        float2 fx0 = __half22float2(hx0[i]);
        float2 fy0 = __half22float2(hy0[i]);
        float2 fx1 = __half22float2(hx1[i]);
        float2 fy1 = __half22float2(hy1[i]);
        s0 = fmaf(fx0.x, fy0.x, s0);
        s0 = fmaf(fx0.y, fy0.y, s0);
        s1 = fmaf(fx1.x, fy1.x, s1);
        s1 = fmaf(fx1.y, fy1.y, s1);
    }

#pragma unroll
    for (int m = 2; m >= 1; m >>= 1) {
        s0 += __shfl_xor_sync(0xffffffffu, s0, m);
        s1 += __shfl_xor_sync(0xffffffffu, s1, m);
    }

    if (sub == 0) {
        float2 o = make_float2(s0 * 0.17677669529663687f,
                               s1 * 0.17677669529663687f);  // 32^-0.5
        *reinterpret_cast<float2*>(out + lid0) = o;
    }
}

extern "C" void kernel_launch(void* const* d_in, const int* in_sizes, int n_in,
                              void* d_out, int out_size)
{
    const float* features = (const float*)d_in[0];
    const float* ks_w     = (const float*)d_in[1];
    const float* ks_b     = (const float*)d_in[2];
    const float* qs_w     = (const float*)d_in[3];
    const float* qs_b     = (const float*)d_in[4];
    const void*  indices  = d_in[5];
    float*       out      = (float*)d_out;

    // 128 threads = 4 warps = 128 rows per block
    proj_kernel<true><<<ROWS / 128, 128>>>(features, ks_w, ks_b, qs_w, qs_b,
                                           (const int*)indices);
    // 4 lanes x (BNK/2) logit-pairs
    affinity_kernel<<<(size_t)(BNK / 2) * 4 / 256, 256>>>(indices, out);
}

// round 8
// speedup vs baseline: 2.7301x; 2.0120x over previous
#include <cuda_runtime.h>
#include <cuda_fp16.h>
#include <cstdint>

#define LATENT 128
#define DQ 32            // KQ_DIM
#define BATCH 8
#define NN 16384
#define KK 16
#define ROWS (BATCH * NN)            // 131072
#define BNK  (BATCH * NN * KK)       // 2097152

// combined projection table, fp16: row r has 64 halves = ks[0:32) | qs[32:64)
__device__ __align__(128) __half g_kq[ROWS * 64];
__device__ int g_idx_is64;

__device__ __forceinline__ unsigned f2tf32(float x) {
    unsigned r;
    asm("cvt.rna.tf32.f32 %0, %1;" : "=r"(r) : "f"(x));
    return r;
}

__device__ __forceinline__ void mma_tf32(float* d,
                                         unsigned a0, unsigned a1,
                                         unsigned a2, unsigned a3,
                                         unsigned b0, unsigned b1) {
    asm volatile(
        "mma.sync.aligned.m16n8k8.row.col.f32.tf32.tf32.f32 "
        "{%0,%1,%2,%3}, {%4,%5,%6,%7}, {%8,%9}, {%0,%1,%2,%3};"
        : "+f"(d[0]), "+f"(d[1]), "+f"(d[2]), "+f"(d[3])
        : "r"(a0), "r"(a1), "r"(a2), "r"(a3), "r"(b0), "r"(b1));
}

// ---------------------------------------------------------------------------
// Phase 1 (tensor-core GEMM): g_kq[row][n] = features[row].W[n] + b[n]
// (n<32: ks, n>=32: qs), stored fp16.
// mma.sync m16n8k8 tf32, 3-pass hi/lo split for fp32-grade accuracy:
//   D += A_hi B_hi;  D += A_lo B_hi;  D += A_hi B_lo   (lo*lo ~ 2^-22, dropped)
// Each warp: 32 rows x 64 outputs (2 m-tiles x 8 n-tiles), 16 K-steps.
// Fragment layout (lane = g*4+tig, g=lane>>2, tig=lane&3):
//   A: a0=(row g,k0) a1=(row g+8,k0) a2=(row g,k0+4) a3=(row g+8,k0+4)
//   B: b0=(k0, n=g)  b1=(k0+4, n=g)      [B = W^T, i.e. B[k][n] = W[n][k]]
//   D: c0=(g,2tig) c1=(g,2tig+1) c2=(g+8,2tig) c3=(g+8,2tig+1)
// Weights in shared [64][132] (pad 4 -> B LDS conflict-free: bank = 4g+tig).
// Block 0 / warp 0 detects index dtype (odd 32-bit words of small nonneg
// int64 are all zero; impossible for 256 genuine int32 indices).
// ---------------------------------------------------------------------------
#define WPAD 132

template <bool DO_DETECT>
__global__ void __launch_bounds__(128)
proj_mma_kernel(const float* __restrict__ features,
                const float* __restrict__ ks_w, const float* __restrict__ ks_b,
                const float* __restrict__ qs_w, const float* __restrict__ qs_b,
                const int*   __restrict__ idx32)
{
    if (DO_DETECT && blockIdx.x == 0 && threadIdx.x < 32) {
        int lane = threadIdx.x;
        int all_hi_zero = 1;
        for (int i = lane; i < 256; i += 32)
            if (idx32[2 * i + 1] != 0) all_hi_zero = 0;
        all_hi_zero = __all_sync(0xffffffffu, all_hi_zero);
        if (lane == 0) g_idx_is64 = all_hi_zero;
    }

    __shared__ float wsh[64 * WPAD];   // wsh[n][k] = W_combined[n][k]
    __shared__ float bsh[64];

    for (int i = threadIdx.x; i < DQ * LATENT; i += 128) {
        int n = i >> 7;            // W row-major [32][128]
        int k = i & 127;
        wsh[n * WPAD + k]        = ks_w[i];
        wsh[(n + 32) * WPAD + k] = qs_w[i];
    }
    if (threadIdx.x < 32) {
        bsh[threadIdx.x]      = ks_b[threadIdx.x];
        bsh[threadIdx.x + 32] = qs_b[threadIdx.x];
    }
    __syncthreads();

    int warp = threadIdx.x >> 5;
    int lane = threadIdx.x & 31;
    int g    = lane >> 2;
    int tig  = lane & 3;

    int rb = (blockIdx.x * 4 + warp) * 32;     // this warp: rows rb..rb+31

    // D[mt][nt][0..3]
    float D[2][8][4];
#pragma unroll
    for (int nt = 0; nt < 8; nt++) {
        float b0 = bsh[nt * 8 + 2 * tig];
        float b1 = bsh[nt * 8 + 2 * tig + 1];
#pragma unroll
        for (int mt = 0; mt < 2; mt++) {
            D[mt][nt][0] = b0; D[mt][nt][1] = b1;
            D[mt][nt][2] = b0; D[mt][nt][3] = b1;
        }
    }

    // row pointers for the 4 A-rows this thread touches (r = 0..3 -> rb+8r+g)
    const float* rp0 = features + (size_t)(rb      + g) * LATENT;
    const float* rp1 = features + (size_t)(rb + 8  + g) * LATENT;
    const float* rp2 = features + (size_t)(rb + 16 + g) * LATENT;
    const float* rp3 = features + (size_t)(rb + 24 + g) * LATENT;

#pragma unroll 4
    for (int ks = 0; ks < 16; ks++) {
        int k0 = ks * 8 + tig;

        float fv[4][2];
        fv[0][0] = rp0[k0]; fv[0][1] = rp0[k0 + 4];
        fv[1][0] = rp1[k0]; fv[1][1] = rp1[k0 + 4];
        fv[2][0] = rp2[k0]; fv[2][1] = rp2[k0 + 4];
        fv[3][0] = rp3[k0]; fv[3][1] = rp3[k0 + 4];

        unsigned ah[4][2], al[4][2];
#pragma unroll
        for (int r = 0; r < 4; r++)
#pragma unroll
            for (int c = 0; c < 2; c++) {
                float x = fv[r][c];
                unsigned h = f2tf32(x);
                ah[r][c] = h;
                al[r][c] = f2tf32(x - __uint_as_float(h));
            }

#pragma unroll
        for (int nt = 0; nt < 8; nt++) {
            const float* wp = wsh + (nt * 8 + g) * WPAD + k0;
            float b0f = wp[0];
            float b1f = wp[4];
            unsigned b0h = f2tf32(b0f);
            unsigned b1h = f2tf32(b1f);
            unsigned b0l = f2tf32(b0f - __uint_as_float(b0h));
            unsigned b1l = f2tf32(b1f - __uint_as_float(b1h));

#pragma unroll
            for (int mt = 0; mt < 2; mt++) {
                int r0 = 2 * mt, r1 = 2 * mt + 1;
                mma_tf32(D[mt][nt], ah[r0][0], ah[r1][0], ah[r0][1], ah[r1][1], b0h, b1h);
                mma_tf32(D[mt][nt], al[r0][0], al[r1][0], al[r0][1], al[r1][1], b0h, b1h);
                mma_tf32(D[mt][nt], ah[r0][0], ah[r1][0], ah[r0][1], ah[r1][1], b0l, b1l);
            }
        }
    }

    // store fp16 into combined table
#pragma unroll
    for (int mt = 0; mt < 2; mt++) {
        int row0 = rb + mt * 16 + g;
#pragma unroll
        for (int nt = 0; nt < 8; nt++) {
            __half2 h01 = __floats2half2_rn(D[mt][nt][0], D[mt][nt][1]);
            __half2 h23 = __floats2half2_rn(D[mt][nt][2], D[mt][nt][3]);
            *reinterpret_cast<__half2*>(
                g_kq + (size_t)row0 * 64 + nt * 8 + 2 * tig) = h01;
            *reinterpret_cast<__half2*>(
                g_kq + (size_t)(row0 + 8) * 64 + nt * 8 + 2 * tig) = h23;
        }
    }
}

// ---------------------------------------------------------------------------
// Phase 2: out[b,n,k] = (ks[b,x_idx] . qs[b,y_idx]) * 32^-0.5, fp16 tables.
// 4 lanes per logit (64B rows); each 4-lane group handles TWO adjacent logits
// (4 independent 16B gathers in flight per thread). 2x shfl_xor reduces
// within the group; lane 0 stores a float2.
// ---------------------------------------------------------------------------
__global__ void __launch_bounds__(256)
affinity_kernel(const void* __restrict__ indices_raw, float* __restrict__ out)
{
    int t   = blockIdx.x * 256 + threadIdx.x;
    int g   = t >> 2;                 // logit-pair id, < BNK/2
    int sub = t & 3;

    int lid0 = g << 1;
    int lid1 = lid0 | 1;
    int b    = lid0 >> 18;            // N*K = 2^18 (pair shares batch)

    long long x0, y0, x1, y1;
    if (g_idx_is64) {
        const long long* idx = (const long long*)indices_raw;
        x0 = idx[(size_t)BNK + lid0];
        x1 = idx[(size_t)BNK + lid1];
        y0 = idx[(size_t)2 * BNK + lid0];
        y1 = idx[(size_t)2 * BNK + lid1];
    } else {
        const int* idx = (const int*)indices_raw;
        x0 = idx[(size_t)BNK + lid0];
        x1 = idx[(size_t)BNK + lid1];
        y0 = idx[(size_t)2 * BNK + lid0];
        y1 = idx[(size_t)2 * BNK + lid1];
    }

    size_t base = (size_t)b << 14;
    const uint4* px0 = reinterpret_cast<const uint4*>(g_kq + ((base + (size_t)x0) << 6)) + sub;
    const uint4* py0 = reinterpret_cast<const uint4*>(g_kq + ((base + (size_t)y0) << 6) + 32) + sub;
    const uint4* px1 = reinterpret_cast<const uint4*>(g_kq + ((base + (size_t)x1) << 6)) + sub;
    const uint4* py1 = reinterpret_cast<const uint4*>(g_kq + ((base + (size_t)y1) << 6) + 32) + sub;

    uint4 ax0 = *px0;
    uint4 ay0 = *py0;
    uint4 ax1 = *px1;
    uint4 ay1 = *py1;

    const __half2* hx0 = reinterpret_cast<const __half2*>(&ax0);
    const __half2* hy0 = reinterpret_cast<const __half2*>(&ay0);
    const __half2* hx1 = reinterpret_cast<const __half2*>(&ax1);
    const __half2* hy1 = reinterpret_cast<const __half2*>(&ay1);

    float s0 = 0.0f, s1 = 0.0f;
#pragma unroll
    for (int i = 0; i < 4; i++) {
        float2 fx0 = __half22float2(hx0[i]);
        float2 fy0 = __half22float2(hy0[i]);
        float2 fx1 = __half22float2(hx1[i]);
        float2 fy1 = __half22float2(hy1[i]);
        s0 = fmaf(fx0.x, fy0.x, s0);
        s0 = fmaf(fx0.y, fy0.y, s0);
        s1 = fmaf(fx1.x, fy1.x, s1);
        s1 = fmaf(fx1.y, fy1.y, s1);
    }

#pragma unroll
    for (int m = 2; m >= 1; m >>= 1) {
        s0 += __shfl_xor_sync(0xffffffffu, s0, m);
        s1 += __shfl_xor_sync(0xffffffffu, s1, m);
    }

    if (sub == 0) {
        float2 o = make_float2(s0 * 0.17677669529663687f,
                               s1 * 0.17677669529663687f);  // 32^-0.5
        *reinterpret_cast<float2*>(out + lid0) = o;
    }
}

extern "C" void kernel_launch(void* const* d_in, const int* in_sizes, int n_in,
                              void* d_out, int out_size)
{
    const float* features = (const float*)d_in[0];
    const float* ks_w     = (const float*)d_in[1];
    const float* ks_b     = (const float*)d_in[2];
    const float* qs_w     = (const float*)d_in[3];
    const float* qs_b     = (const float*)d_in[4];
    const void*  indices  = d_in[5];
    float*       out      = (float*)d_out;

    // 128 threads = 4 warps x 32 rows = 128 rows per block
    proj_mma_kernel<true><<<ROWS / 128, 128>>>(features, ks_w, ks_b, qs_w, qs_b,
                                               (const int*)indices);
    // 4 lanes x (BNK/2) logit-pairs
    affinity_kernel<<<(size_t)(BNK / 2) * 4 / 256, 256>>>(indices, out);
}

// round 9
// speedup vs baseline: 3.2778x; 1.2006x over previous
#include <cuda_runtime.h>
#include <cuda_fp16.h>
#include <cstdint>

#define LATENT 128
#define DQ 32            // KQ_DIM
#define BATCH 8
#define NN 16384
#define KK 16
#define ROWS (BATCH * NN)            // 131072
#define BNK  (BATCH * NN * KK)       // 2097152

// combined projection table, fp16: row r has 64 halves = ks[0:32) | qs[32:64)
__device__ __align__(128) __half g_kq[ROWS * 64];
__device__ int g_idx_is64;

typedef unsigned u32;

// pack two floats to bf16x2: result = {hi:a, lo:b} for cvt(a, b)
__device__ __forceinline__ u32 cvt_bf16x2(float hi, float lo) {
    u32 r;
    asm("cvt.rn.bf16x2.f32 %0, %1, %2;" : "=r"(r) : "f"(hi), "f"(lo));
    return r;
}
__device__ __forceinline__ float bf16lo_f(u32 p) { return __uint_as_float(p << 16); }
__device__ __forceinline__ float bf16hi_f(u32 p) { return __uint_as_float(p & 0xffff0000u); }

__device__ __forceinline__ void mma_bf16(float* d,
                                         u32 a0, u32 a1, u32 a2, u32 a3,
                                         u32 b0, u32 b1) {
    asm volatile(
        "mma.sync.aligned.m16n8k16.row.col.f32.bf16.bf16.f32 "
        "{%0,%1,%2,%3}, {%4,%5,%6,%7}, {%8,%9}, {%0,%1,%2,%3};"
        : "+f"(d[0]), "+f"(d[1]), "+f"(d[2]), "+f"(d[3])
        : "r"(a0), "r"(a1), "r"(a2), "r"(a3), "r"(b0), "r"(b1));
}

// ---------------------------------------------------------------------------
// Phase 1 (bf16-split tensor GEMM): g_kq[row][n] = features[row].W[n] + b[n]
// (n<32: ks, n>=32: qs), stored fp16.
// x = x_hi(bf16) + x_lo(bf16 of residual); D += Ah Bh + Al Bh + Ah Bl
// (lo*lo ~ 2^-16, dropped; fp16 storage error dominates).
// Each warp: 32 rows x 64 outputs (2 m-tiles x 8 n-tiles), 8 K-steps (K=16).
// m16n8k16 fragments (lane = g*4+tig):
//   A: a0={r g,k 2tig..+1} a1={r g+8} a2={r g,k+8} a3={r g+8,k+8}
//   B: b0={k 2tig..+1, n g} b1={k+8..}   [B = W^T]
//   D: c0={g,2tig} c1={g,2tig+1} c2={g+8,2tig} c3={g+8,2tig+1}
// Weight hi/lo bf16x2 precomputed ONCE per block into shared, stride 68
// words -> B-fragment LDS bank = 4g+tig, conflict-free.
// Block 0 / warp 0 detects index dtype (odd 32-bit words of small nonneg
// int64 are all zero; impossible for 256 genuine int32 indices).
// ---------------------------------------------------------------------------
#define WST 68   // shared stride in u32 for weight pair arrays

template <bool DO_DETECT>
__global__ void __launch_bounds__(128)
proj_mma_kernel(const float* __restrict__ features,
                const float* __restrict__ ks_w, const float* __restrict__ ks_b,
                const float* __restrict__ qs_w, const float* __restrict__ qs_b,
                const int*   __restrict__ idx32)
{
    if (DO_DETECT && blockIdx.x == 0 && threadIdx.x < 32) {
        int lane = threadIdx.x;
        int all_hi_zero = 1;
        for (int i = lane; i < 256; i += 32)
            if (idx32[2 * i + 1] != 0) all_hi_zero = 0;
        all_hi_zero = __all_sync(0xffffffffu, all_hi_zero);
        if (lane == 0) g_idx_is64 = all_hi_zero;
    }

    // whp_hi/whp_lo[n][p]: bf16x2 of W_combined[n][2p..2p+1], hi/lo split
    __shared__ u32 whp_hi[64 * WST];
    __shared__ u32 whp_lo[64 * WST];
    __shared__ float bsh[64];

    for (int i = threadIdx.x; i < 64 * 64; i += 128) {
        int n = i >> 6;                 // combined output 0..63
        int p = i & 63;                 // k-pair 0..63
        const float* src = (n < 32) ? (ks_w + n * LATENT) : (qs_w + (n - 32) * LATENT);
        float w0 = src[2 * p];
        float w1 = src[2 * p + 1];
        u32 hi = cvt_bf16x2(w1, w0);
        float l0 = w0 - bf16lo_f(hi);
        float l1 = w1 - bf16hi_f(hi);
        whp_hi[n * WST + p] = hi;
        whp_lo[n * WST + p] = cvt_bf16x2(l1, l0);
    }
    if (threadIdx.x < 32) {
        bsh[threadIdx.x]      = ks_b[threadIdx.x];
        bsh[threadIdx.x + 32] = qs_b[threadIdx.x];
    }
    __syncthreads();

    int warp = threadIdx.x >> 5;
    int lane = threadIdx.x & 31;
    int g    = lane >> 2;
    int tig  = lane & 3;

    int rb = (blockIdx.x * 4 + warp) * 32;     // this warp: rows rb..rb+31

    float D[2][8][4];
#pragma unroll
    for (int nt = 0; nt < 8; nt++) {
        float b0 = bsh[nt * 8 + 2 * tig];
        float b1 = bsh[nt * 8 + 2 * tig + 1];
#pragma unroll
        for (int mt = 0; mt < 2; mt++) {
            D[mt][nt][0] = b0; D[mt][nt][1] = b1;
            D[mt][nt][2] = b0; D[mt][nt][3] = b1;
        }
    }

    // A-row pointers: mt tile rows (rb+16mt+g, +8)
    const float* rp[4];
    rp[0] = features + (size_t)(rb      + g) * LATENT;
    rp[1] = features + (size_t)(rb + 8  + g) * LATENT;
    rp[2] = features + (size_t)(rb + 16 + g) * LATENT;
    rp[3] = features + (size_t)(rb + 24 + g) * LATENT;

#pragma unroll
    for (int ks = 0; ks < 8; ks++) {
        int k0 = ks * 16 + 2 * tig;

        // load + split A: per mt, regs {r,k0},{r+8,k0},{r,k0+8},{r+8,k0+8}
        u32 ah[2][4], al[2][4];
#pragma unroll
        for (int mt = 0; mt < 2; mt++) {
            float2 f[4];
            f[0] = *reinterpret_cast<const float2*>(rp[2 * mt]     + k0);
            f[1] = *reinterpret_cast<const float2*>(rp[2 * mt + 1] + k0);
            f[2] = *reinterpret_cast<const float2*>(rp[2 * mt]     + k0 + 8);
            f[3] = *reinterpret_cast<const float2*>(rp[2 * mt + 1] + k0 + 8);
#pragma unroll
            for (int r = 0; r < 4; r++) {
                u32 h = cvt_bf16x2(f[r].y, f[r].x);
                ah[mt][r] = h;
                float lx = f[r].x - bf16lo_f(h);
                float ly = f[r].y - bf16hi_f(h);
                al[mt][r] = cvt_bf16x2(ly, lx);
            }
        }

#pragma unroll
        for (int nt = 0; nt < 8; nt++) {
            int base = (nt * 8 + g) * WST + ks * 8 + tig;
            u32 b0h = whp_hi[base];
            u32 b1h = whp_hi[base + 4];
            u32 b0l = whp_lo[base];
            u32 b1l = whp_lo[base + 4];
#pragma unroll
            for (int mt = 0; mt < 2; mt++) {
                mma_bf16(D[mt][nt], ah[mt][0], ah[mt][1], ah[mt][2], ah[mt][3], b0h, b1h);
                mma_bf16(D[mt][nt], al[mt][0], al[mt][1], al[mt][2], al[mt][3], b0h, b1h);
                mma_bf16(D[mt][nt], ah[mt][0], ah[mt][1], ah[mt][2], ah[mt][3], b0l, b1l);
            }
        }
    }

    // store fp16 into combined table
#pragma unroll
    for (int mt = 0; mt < 2; mt++) {
        int row0 = rb + mt * 16 + g;
#pragma unroll
        for (int nt = 0; nt < 8; nt++) {
            __half2 h01 = __floats2half2_rn(D[mt][nt][0], D[mt][nt][1]);
            __half2 h23 = __floats2half2_rn(D[mt][nt][2], D[mt][nt][3]);
            *reinterpret_cast<__half2*>(
                g_kq + (size_t)row0 * 64 + nt * 8 + 2 * tig) = h01;
            *reinterpret_cast<__half2*>(
                g_kq + (size_t)(row0 + 8) * 64 + nt * 8 + 2 * tig) = h23;
        }
    }
}

// ---------------------------------------------------------------------------
// Phase 2: out[b,n,k] = (ks[b,x_idx] . qs[b,y_idx]) * 32^-0.5, fp16 tables.
// 4 lanes per logit (64B half-rows); each 4-lane group handles TWO adjacent
// logits (4 independent 16B gathers in flight per thread). 2x shfl_xor
// reduces within the group; lane 0 stores a float2.
// ---------------------------------------------------------------------------
__global__ void __launch_bounds__(256)
affinity_kernel(const void* __restrict__ indices_raw, float* __restrict__ out)
{
    int t   = blockIdx.x * 256 + threadIdx.x;
    int g   = t >> 2;                 // logit-pair id, < BNK/2
    int sub = t & 3;

    int lid0 = g << 1;
    int lid1 = lid0 | 1;
    int b    = lid0 >> 18;            // N*K = 2^18 (pair shares batch)

    long long x0, y0, x1, y1;
    if (g_idx_is64) {
        const long long* idx = (const long long*)indices_raw;
        x0 = idx[(size_t)BNK + lid0];
        x1 = idx[(size_t)BNK + lid1];
        y0 = idx[(size_t)2 * BNK + lid0];
        y1 = idx[(size_t)2 * BNK + lid1];
    } else {
        const int* idx = (const int*)indices_raw;
        x0 = idx[(size_t)BNK + lid0];
        x1 = idx[(size_t)BNK + lid1];
        y0 = idx[(size_t)2 * BNK + lid0];
        y1 = idx[(size_t)2 * BNK + lid1];
    }

    size_t base = (size_t)b << 14;
    const uint4* px0 = reinterpret_cast<const uint4*>(g_kq + ((base + (size_t)x0) << 6)) + sub;
    const uint4* py0 = reinterpret_cast<const uint4*>(g_kq + ((base + (size_t)y0) << 6) + 32) + sub;
    const uint4* px1 = reinterpret_cast<const uint4*>(g_kq + ((base + (size_t)x1) << 6)) + sub;
    const uint4* py1 = reinterpret_cast<const uint4*>(g_kq + ((base + (size_t)y1) << 6) + 32) + sub;

    uint4 ax0 = *px0;
    uint4 ay0 = *py0;
    uint4 ax1 = *px1;
    uint4 ay1 = *py1;

    const __half2* hx0 = reinterpret_cast<const __half2*>(&ax0);
    const __half2* hy0 = reinterpret_cast<const __half2*>(&ay0);
    const __half2* hx1 = reinterpret_cast<const __half2*>(&ax1);
    const __half2* hy1 = reinterpret_cast<const __half2*>(&ay1);

    float s0 = 0.0f, s1 = 0.0f;
#pragma unroll
    for (int i = 0; i < 4; i++) {
        float2 fx0 = __half22float2(hx0[i]);
        float2 fy0 = __half22float2(hy0[i]);
        float2 fx1 = __half22float2(hx1[i]);
        float2 fy1 = __half22float2(hy1[i]);
        s0 = fmaf(fx0.x, fy0.x, s0);
        s0 = fmaf(fx0.y, fy0.y, s0);
        s1 = fmaf(fx1.x, fy1.x, s1);
        s1 = fmaf(fx1.y, fy1.y, s1);
    }

#pragma unroll
    for (int m = 2; m >= 1; m >>= 1) {
        s0 += __shfl_xor_sync(0xffffffffu, s0, m);
        s1 += __shfl_xor_sync(0xffffffffu, s1, m);
    }

    if (sub == 0) {
        float2 o = make_float2(s0 * 0.17677669529663687f,
                               s1 * 0.17677669529663687f);  // 32^-0.5
        *reinterpret_cast<float2*>(out + lid0) = o;
    }
}

extern "C" void kernel_launch(void* const* d_in, const int* in_sizes, int n_in,
                              void* d_out, int out_size)
{
    const float* features = (const float*)d_in[0];
    const float* ks_w     = (const float*)d_in[1];
    const float* ks_b     = (const float*)d_in[2];
    const float* qs_w     = (const float*)d_in[3];
    const float* qs_b     = (const float*)d_in[4];
    const void*  indices  = d_in[5];
    float*       out      = (float*)d_out;

    // 128 threads = 4 warps x 32 rows = 128 rows per block
    proj_mma_kernel<true><<<ROWS / 128, 128>>>(features, ks_w, ks_b, qs_w, qs_b,
                                               (const int*)indices);
    // 4 lanes x (BNK/2) logit-pairs
    affinity_kernel<<<(size_t)(BNK / 2) * 4 / 256, 256>>>(indices, out);
}

// round 11
// speedup vs baseline: 3.2901x; 1.0037x over previous
#include <cuda_runtime.h>
#include <cuda_fp16.h>
#include <cstdint>

#define LATENT 128
#define DQ 32            // KQ_DIM
#define BATCH 8
#define NN 16384
#define KK 16
#define ROWS (BATCH * NN)            // 131072
#define BNK  (BATCH * NN * KK)       // 2097152

// combined projection table, fp16: row r has 64 halves = ks[0:32) | qs[32:64)
__device__ __align__(128) __half g_kq[ROWS * 64];
__device__ int g_idx_is64;

typedef unsigned u32;

// pack two floats to bf16x2: result = {hi:a, lo:b} for cvt(a, b)
__device__ __forceinline__ u32 cvt_bf16x2(float hi, float lo) {
    u32 r;
    asm("cvt.rn.bf16x2.f32 %0, %1, %2;" : "=r"(r) : "f"(hi), "f"(lo));
    return r;
}
__device__ __forceinline__ float bf16lo_f(u32 p) { return __uint_as_float(p << 16); }
__device__ __forceinline__ float bf16hi_f(u32 p) { return __uint_as_float(p & 0xffff0000u); }

__device__ __forceinline__ void mma_bf16(float* d,
                                         u32 a0, u32 a1, u32 a2, u32 a3,
                                         u32 b0, u32 b1) {
    asm volatile(
        "mma.sync.aligned.m16n8k16.row.col.f32.bf16.bf16.f32 "
        "{%0,%1,%2,%3}, {%4,%5,%6,%7}, {%8,%9}, {%0,%1,%2,%3};"
        : "+f"(d[0]), "+f"(d[1]), "+f"(d[2]), "+f"(d[3])
        : "r"(a0), "r"(a1), "r"(a2), "r"(a3), "r"(b0), "r"(b1));
}

// ---------------------------------------------------------------------------
// Phase 1 (bf16-split tensor GEMM): g_kq[row][n] = features[row].W[n] + b[n]
// (n<32: ks, n>=32: qs), stored fp16.
// x = x_hi(bf16) + x_lo(bf16 of residual); D += Ah Bh + Al Bh + Ah Bl
// (lo*lo ~ 2^-16 dropped; fp16 storage error dominates).
// Each warp: 32 rows x 64 outputs (2 m-tiles x 8 n-tiles), 8 K-steps (K=16).
// A feature loads are double-buffered across k-steps so the LDG.64 latency
// overlaps the MMA block of the previous step.
// Weight hi/lo bf16x2 precomputed once per block into shared, stride 68
// words -> B-fragment LDS bank = 4g+tig, conflict-free.
// Block 0 / warp 0 detects index dtype (odd 32-bit words of small nonneg
// int64 are all zero; impossible for 256 genuine int32 indices).
// ---------------------------------------------------------------------------
#define WST 68   // shared stride in u32 for weight pair arrays

template <bool DO_DETECT>
__global__ void __launch_bounds__(128)
proj_mma_kernel(const float* __restrict__ features,
                const float* __restrict__ ks_w, const float* __restrict__ ks_b,
                const float* __restrict__ qs_w, const float* __restrict__ qs_b,
                const int*   __restrict__ idx32)
{
    if (DO_DETECT && blockIdx.x == 0 && threadIdx.x < 32) {
        int lane = threadIdx.x;
        int all_hi_zero = 1;
        for (int i = lane; i < 256; i += 32)
            if (idx32[2 * i + 1] != 0) all_hi_zero = 0;
        all_hi_zero = __all_sync(0xffffffffu, all_hi_zero);
        if (lane == 0) g_idx_is64 = all_hi_zero;
    }

    // whp_hi/whp_lo[n][p]: bf16x2 of W_combined[n][2p..2p+1], hi/lo split
    __shared__ u32 whp_hi[64 * WST];
    __shared__ u32 whp_lo[64 * WST];
    __shared__ float bsh[64];

    for (int i = threadIdx.x; i < 64 * 64; i += 128) {
        int n = i >> 6;                 // combined output 0..63
        int p = i & 63;                 // k-pair 0..63
        const float* src = (n < 32) ? (ks_w + n * LATENT) : (qs_w + (n - 32) * LATENT);
        float w0 = src[2 * p];
        float w1 = src[2 * p + 1];
        u32 hi = cvt_bf16x2(w1, w0);
        float l0 = w0 - bf16lo_f(hi);
        float l1 = w1 - bf16hi_f(hi);
        whp_hi[n * WST + p] = hi;
        whp_lo[n * WST + p] = cvt_bf16x2(l1, l0);
    }
    if (threadIdx.x < 32) {
        bsh[threadIdx.x]      = ks_b[threadIdx.x];
        bsh[threadIdx.x + 32] = qs_b[threadIdx.x];
    }
    __syncthreads();

    int warp = threadIdx.x >> 5;
    int lane = threadIdx.x & 31;
    int g    = lane >> 2;
    int tig  = lane & 3;

    int rb = (blockIdx.x * 4 + warp) * 32;     // this warp: rows rb..rb+31

    float D[2][8][4];
#pragma unroll
    for (int nt = 0; nt < 8; nt++) {
        float b0 = bsh[nt * 8 + 2 * tig];
        float b1 = bsh[nt * 8 + 2 * tig + 1];
#pragma unroll
        for (int mt = 0; mt < 2; mt++) {
            D[mt][nt][0] = b0; D[mt][nt][1] = b1;
            D[mt][nt][2] = b0; D[mt][nt][3] = b1;
        }
    }

    // A-row pointers: thread touches rows rb + {0,8,16,24} + g
    const float* rp[4];
    rp[0] = features + (size_t)(rb      + g) * LATENT;
    rp[1] = features + (size_t)(rb + 8  + g) * LATENT;
    rp[2] = features + (size_t)(rb + 16 + g) * LATENT;
    rp[3] = features + (size_t)(rb + 24 + g) * LATENT;

    // double-buffered A: f[mt*2 + hi/lo half][...]  (8 float2 per k-step)
    float2 fbuf[2][8];
    {
        int k0 = 2 * tig;
#pragma unroll
        for (int mt = 0; mt < 2; mt++) {
            fbuf[0][mt * 4 + 0] = *reinterpret_cast<const float2*>(rp[2 * mt]     + k0);
            fbuf[0][mt * 4 + 1] = *reinterpret_cast<const float2*>(rp[2 * mt + 1] + k0);
            fbuf[0][mt * 4 + 2] = *reinterpret_cast<const float2*>(rp[2 * mt]     + k0 + 8);
            fbuf[0][mt * 4 + 3] = *reinterpret_cast<const float2*>(rp[2 * mt + 1] + k0 + 8);
        }
    }

#pragma unroll
    for (int ks = 0; ks < 8; ks++) {
        int cur = ks & 1;
        // prefetch next k-step
        if (ks < 7) {
            int k0 = (ks + 1) * 16 + 2 * tig;
#pragma unroll
            for (int mt = 0; mt < 2; mt++) {
                fbuf[cur ^ 1][mt * 4 + 0] = *reinterpret_cast<const float2*>(rp[2 * mt]     + k0);
                fbuf[cur ^ 1][mt * 4 + 1] = *reinterpret_cast<const float2*>(rp[2 * mt + 1] + k0);
                fbuf[cur ^ 1][mt * 4 + 2] = *reinterpret_cast<const float2*>(rp[2 * mt]     + k0 + 8);
                fbuf[cur ^ 1][mt * 4 + 3] = *reinterpret_cast<const float2*>(rp[2 * mt + 1] + k0 + 8);
            }
        }

        // split A
        u32 ah[2][4], al[2][4];
#pragma unroll
        for (int mt = 0; mt < 2; mt++)
#pragma unroll
            for (int r = 0; r < 4; r++) {
                float2 f = fbuf[cur][mt * 4 + r];
                u32 h = cvt_bf16x2(f.y, f.x);
                ah[mt][r] = h;
                al[mt][r] = cvt_bf16x2(f.y - bf16hi_f(h), f.x - bf16lo_f(h));
            }

#pragma unroll
        for (int nt = 0; nt < 8; nt++) {
            int base = (nt * 8 + g) * WST + ks * 8 + tig;
            u32 b0h = whp_hi[base];
            u32 b1h = whp_hi[base + 4];
            u32 b0l = whp_lo[base];
            u32 b1l = whp_lo[base + 4];
#pragma unroll
            for (int mt = 0; mt < 2; mt++) {
                mma_bf16(D[mt][nt], ah[mt][0], ah[mt][1], ah[mt][2], ah[mt][3], b0h, b1h);
                mma_bf16(D[mt][nt], al[mt][0], al[mt][1], al[mt][2], al[mt][3], b0h, b1h);
                mma_bf16(D[mt][nt], ah[mt][0], ah[mt][1], ah[mt][2], ah[mt][3], b0l, b1l);
            }
        }
    }

    // store fp16 into combined table
#pragma unroll
    for (int mt = 0; mt < 2; mt++) {
        int row0 = rb + mt * 16 + g;
#pragma unroll
        for (int nt = 0; nt < 8; nt++) {
            __half2 h01 = __floats2half2_rn(D[mt][nt][0], D[mt][nt][1]);
            __half2 h23 = __floats2half2_rn(D[mt][nt][2], D[mt][nt][3]);
            *reinterpret_cast<__half2*>(
                g_kq + (size_t)row0 * 64 + nt * 8 + 2 * tig) = h01;
            *reinterpret_cast<__half2*>(
                g_kq + (size_t)(row0 + 8) * 64 + nt * 8 + 2 * tig) = h23;
        }
    }
}

// ---------------------------------------------------------------------------
// Phase 2: out[b,n,k] = (ks[b,x_idx] . qs[b,y_idx]) * 32^-0.5, fp16 tables.
// 4-lane groups, FOUR logits per group: each lane loads its own logit's
// indices, shfl-broadcasts row byte-offsets, and keeps 8 independent 16B
// gathers in flight (MLP=8). 2x shfl_xor reduces each dot; lane 0 of each
// group stores a float4 of 4 logits.
// ---------------------------------------------------------------------------
__global__ void __launch_bounds__(256)
affinity_kernel(const void* __restrict__ indices_raw, float* __restrict__ out)
{
    int t    = blockIdx.x * 256 + threadIdx.x;
    int lane = threadIdx.x & 31;
    int sub  = t & 3;
    int grp  = t >> 2;                 // group id, < BNK/4
    int lid  = (grp << 2) | sub;       // own logit
    int b    = lid >> 18;              // N*K = 2^18 (group shares batch)

    int x, y;
    if (g_idx_is64) {
        const long long* idx = (const long long*)indices_raw;
        x = (int)idx[(size_t)BNK + lid];
        y = (int)idx[(size_t)2 * BNK + lid];
    } else {
        const int* idx = (const int*)indices_raw;
        x = idx[(size_t)BNK + lid];
        y = idx[(size_t)2 * BNK + lid];
    }

    int base = b << 14;
    u32 offx = (u32)((base + x) << 7);        // 128B rows; ks = first 64B
    u32 offy = (u32)(((base + y) << 7) + 64); // qs = second 64B

    const char* tab = reinterpret_cast<const char*>(g_kq);

    float s[4];
#pragma unroll
    for (int j = 0; j < 4; j++) {
        u32 ox = __shfl_sync(0xffffffffu, offx, (lane & 28) | j);
        u32 oy = __shfl_sync(0xffffffffu, offy, (lane & 28) | j);
        uint4 ax = *(reinterpret_cast<const uint4*>(tab + ox) + sub);
        uint4 ay = *(reinterpret_cast<const uint4*>(tab + oy) + sub);
        const __half2* hx = reinterpret_cast<const __half2*>(&ax);
        const __half2* hy = reinterpret_cast<const __half2*>(&ay);
        float sj = 0.0f;
#pragma unroll
        for (int i = 0; i < 4; i++) {
            float2 fx = __half22float2(hx[i]);
            float2 fy = __half22float2(hy[i]);
            sj = fmaf(fx.x, fy.x, sj);
            sj = fmaf(fx.y, fy.y, sj);
        }
        s[j] = sj;
    }

#pragma unroll
    for (int j = 0; j < 4; j++) {
        s[j] += __shfl_xor_sync(0xffffffffu, s[j], 2);
        s[j] += __shfl_xor_sync(0xffffffffu, s[j], 1);
    }

    if (sub == 0) {
        const float C = 0.17677669529663687f;  // 32^-0.5
        float4 o = make_float4(s[0] * C, s[1] * C, s[2] * C, s[3] * C);
        *reinterpret_cast<float4*>(out + (grp << 2)) = o;
    }
}

extern "C" void kernel_launch(void* const* d_in, const int* in_sizes, int n_in,
                              void* d_out, int out_size)
{
    const float* features = (const float*)d_in[0];
    const float* ks_w     = (const float*)d_in[1];
    const float* ks_b     = (const float*)d_in[2];
    const float* qs_w     = (const float*)d_in[3];
    const float* qs_b     = (const float*)d_in[4];
    const void*  indices  = d_in[5];
    float*       out      = (float*)d_out;

    // 128 threads = 4 warps x 32 rows = 128 rows per block
    proj_mma_kernel<true><<<ROWS / 128, 128>>>(features, ks_w, ks_b, qs_w, qs_b,
                                               (const int*)indices);
    // one 4-lane group per 4 logits
    affinity_kernel<<<BNK / 256, 256>>>(indices, out);
}